// round 13
// baseline (speedup 1.0000x reference)
#include <cuda_runtime.h>
#include <cuda_fp16.h>
#include <cstdint>
#include <math.h>

#define B_  32
#define LQ  512
#define LS  1024
#define DD  1024
#define SS  256
#define EPSF 1e-8f

// Scratch (allocation forbidden): device globals.
__device__ __half g_qmh [B_ * LQ * DD];   // fp16(query*matrix)   32MB
__device__ __half g_ctxh[B_ * LS * DD];   // fp16(ctx)            64MB
__device__ __half g_ctxt[B_ * DD * LS];   // fp16(ctx^T)          64MB
__device__ __half g_attn[B_ * LQ * LS];   // attn (b,q,s) fp16    32MB
__device__ __half g_wch [B_ * LQ * DD];   // wcontext fp16        32MB
__device__ __half g_wh  [SS * DD];        // fp16(W)              0.5MB
__device__ float  g_cn  [B_ * LS];        // column sumsq (attn)  128KB
__device__ float  g_rn  [B_ * LQ];        // row sumsq (wc)        64KB

// ---------------------------------------------------------------------------
__device__ __forceinline__ uint32_t smem_u32(const void* p) {
    uint32_t a;
    asm("{ .reg .u64 t; cvta.to.shared.u64 t, %1; cvt.u32.u64 %0, t; }"
        : "=r"(a) : "l"(p));
    return a;
}
__device__ __forceinline__ float lrelu(float x) { return x > 0.f ? x : 0.1f * x; }

__device__ __forceinline__ void cp16(uint32_t s, const void* g) {
    asm volatile("cp.async.cg.shared.global [%0], [%1], 16;" :: "r"(s), "l"(g));
}
__device__ __forceinline__ void cp_commit() {
    asm volatile("cp.async.commit_group;" ::: "memory");
}
template <int N> __device__ __forceinline__ void cp_wait() {
    asm volatile("cp.async.wait_group %0;" :: "n"(N) : "memory");
}

__device__ __forceinline__ void mma16(float* c, const uint32_t* a, const uint32_t* b) {
    asm volatile(
        "mma.sync.aligned.m16n8k16.row.col.f32.f16.f16.f32 "
        "{%0,%1,%2,%3}, {%4,%5,%6,%7}, {%8,%9}, {%0,%1,%2,%3};"
        : "+f"(c[0]), "+f"(c[1]), "+f"(c[2]), "+f"(c[3])
        : "r"(a[0]), "r"(a[1]), "r"(a[2]), "r"(a[3]), "r"(b[0]), "r"(b[1]));
}
__device__ __forceinline__ void ldsm4(uint32_t* r, uint32_t addr) {
    asm volatile("ldmatrix.sync.aligned.m8n8.x4.shared.b16 {%0,%1,%2,%3}, [%4];"
        : "=r"(r[0]), "=r"(r[1]), "=r"(r[2]), "=r"(r[3]) : "r"(addr));
}

// ---------------------------------------------------------------------------
// fp16 warp-MMA GEMM: D[m,n] = sum_k A[m,k]*B[n,k]  (K=1024, both K-major)
//   EPI 0: CTA 128x128 occ2, 3-stage cp.async. leaky_relu, fp16 store,
//          fused column-sumsq.
//   EPI 1: CTA 128x128 occ2, 3-stage cp.async. fp16 store, fused row-sumsq.
//   EPI 2: CTA 64x256 occ2, 2-stage. A = diff^2 fused loader (wc,qry,rn).
//          +bias, fused l2norm over N=256, fp32 store.
// ---------------------------------------------------------------------------
#define KTOT 1024
#define BKC  64
#define NIT  (KTOT / BKC)       // 16
#define LDB32 36                // row pitch, b32 units
#define ROWB  (LDB32 * 4)       // 144 B

template <int EPI>
__global__ __launch_bounds__(256, 2) void hgemm(
    const __half* __restrict__ gA, const __half* __restrict__ gB,
    void* __restrict__ gDv, const float* __restrict__ bias,
    float* __restrict__ redg,
    const float* __restrict__ qy, const float* __restrict__ rn,
    int lda, int ldb, int ldd, size_t sA, size_t sB, size_t sD)
{
    constexpr int TBM = (EPI == 2) ? 64 : 128;
    constexpr int TBN = (EPI == 2) ? 256 : 128;
    constexpr int TWM = (EPI == 2) ? 1 : 2;
    constexpr int NST = (EPI == 2) ? 2 : 3;
    constexpr int AF  = TBM * LDB32;
    constexpr int BF  = TBN * LDB32;
    constexpr int STF = AF + BF;

    extern __shared__ uint32_t smu[];
    float* redbuf = (float*)(smu + NST * STF);

    const int tid  = threadIdx.x;
    const int wid  = tid >> 5, lane = tid & 31;
    const int m0   = blockIdx.y * TBM, n0 = blockIdx.x * TBN, z = blockIdx.z;
    const int wm   = wid % TWM;
    const int wn   = wid / TWM;
    const int gq   = lane >> 2;
    const int gc   = lane & 3;

    const __half* A  = gA + (size_t)z * sA + (size_t)m0 * lda;
    const __half* Bp = gB + (size_t)z * sB + (size_t)n0 * ldb;
    const uint32_t sbase = smem_u32(smu);

    const int lr = lane & 7;
    const uint32_t aoff = (uint32_t)(wm * 64 + lr + ((lane >> 3) & 1) * 8) * ROWB
                        + (uint32_t)(lane >> 4) * 16;
    const uint32_t boff = (uint32_t)(wn * 32 + lr + (lane >> 4) * 8) * ROWB
                        + (uint32_t)((lane >> 3) & 1) * 16 + (uint32_t)AF * 4u;

    if (EPI == 0 && tid < TBN) redbuf[tid] = 0.f;
    if (EPI == 1 && tid < TBM) redbuf[tid] = 0.f;

    // EPI2 fused-A state: thread owns row am, 16 halfs at [aseg*8, aseg*8+16)
    const int am   = tid >> 2;
    const int aseg = (tid & 3) * 2;
    float ainv = 0.f;
    const __half* wcrow = nullptr;
    const float*  qrow  = nullptr;
    if (EPI == 2) {
        ainv  = 1.f / (sqrtf(rn[(size_t)z * LQ + m0 + am]) + EPSF);
        wcrow = gA + (size_t)z * sA + (size_t)(m0 + am) * lda;
        qrow  = qy + (size_t)z * sA + (size_t)(m0 + am) * lda;
    }

    float acc[4][4][4];
#pragma unroll
    for (int i = 0; i < 4; i++)
#pragma unroll
        for (int j = 0; j < 4; j++)
#pragma unroll
            for (int k = 0; k < 4; k++) acc[i][j][k] = 0.f;

    auto load_stage = [&](int stage, int k0) {
        const uint32_t ab = sbase + (uint32_t)(stage * STF) * 4u;
        const uint32_t bb = ab + (uint32_t)AF * 4u;
        if (EPI == 2) {
            // A: diff^2 computed on the fly (sync loads; occ 2 hides latency)
            const __half2* wh = (const __half2*)(wcrow + k0 + aseg * 8);
            const float4 q0 = *(const float4*)(qrow + k0 + aseg * 8);
            const float4 q1 = *(const float4*)(qrow + k0 + aseg * 8 + 4);
            const float4 q2 = *(const float4*)(qrow + k0 + aseg * 8 + 8);
            const float4 q3 = *(const float4*)(qrow + k0 + aseg * 8 + 12);
            const float qq[16] = {q0.x,q0.y,q0.z,q0.w, q1.x,q1.y,q1.z,q1.w,
                                  q2.x,q2.y,q2.z,q2.w, q3.x,q3.y,q3.z,q3.w};
            uint32_t out[8];
#pragma unroll
            for (int j = 0; j < 8; j++) {
                const float2 wf = __half22float2(wh[j]);
                const float d0 = qq[2 * j]     - wf.x * ainv;
                const float d1 = qq[2 * j + 1] - wf.y * ainv;
                const __half2 r = __floats2half2_rn(d0 * d0, d1 * d1);
                out[j] = *(const uint32_t*)&r;
            }
            char* sm8 = (char*)smu + (size_t)stage * STF * 4 + am * ROWB + aseg * 16;
            *(uint4*)sm8        = *(const uint4*)&out[0];
            *(uint4*)(sm8 + 16) = *(const uint4*)&out[4];
        } else {
#pragma unroll
            for (int r = 0; r < TBM * 8 / 256; r++) {
                int u = tid + r * 256;
                int m = u >> 3, seg = u & 7;
                cp16(ab + (uint32_t)(m * ROWB + seg * 16),
                     A + (size_t)m * lda + k0 + seg * 8);
            }
        }
#pragma unroll
        for (int r = 0; r < TBN * 8 / 256; r++) {
            int u = tid + r * 256;
            int n = u >> 3, seg = u & 7;
            cp16(bb + (uint32_t)(n * ROWB + seg * 16),
                 Bp + (size_t)n * ldb + k0 + seg * 8);
        }
        cp_commit();
    };

    auto compute = [&](uint32_t stA) {
#pragma unroll
        for (int ks = 0; ks < 4; ks++) {
            uint32_t af[4][4], bf[4][2];
#pragma unroll
            for (int mt = 0; mt < 4; mt++)
                ldsm4(af[mt], stA + ks * 32 + aoff + (uint32_t)(mt * 16 * ROWB));
#pragma unroll
            for (int np = 0; np < 2; np++) {
                uint32_t t[4];
                ldsm4(t, stA + ks * 32 + boff + (uint32_t)(np * 16 * ROWB));
                bf[np * 2][0] = t[0]; bf[np * 2][1] = t[1];
                bf[np * 2 + 1][0] = t[2]; bf[np * 2 + 1][1] = t[3];
            }
#pragma unroll
            for (int mt = 0; mt < 4; mt++)
#pragma unroll
                for (int nt = 0; nt < 4; nt++)
                    mma16(acc[mt][nt], af[mt], bf[nt]);
        }
    };

    if (EPI == 2) {
        load_stage(0, 0);
        for (int i = 0; i < NIT; i++) {
            cp_wait<0>();
            __syncthreads();
            if (i + 1 < NIT) load_stage((i + 1) & 1, (i + 1) * BKC);
            compute(sbase + (uint32_t)((i & 1) * STF) * 4u);
        }
    } else {
        load_stage(0, 0);
        load_stage(1, BKC);
        for (int i = 0; i < NIT; i++) {
            if (i < NIT - 1) cp_wait<1>(); else cp_wait<0>();
            __syncthreads();
            if (i + 2 < NIT) load_stage((i + 2) % 3, (i + 2) * BKC);
            compute(sbase + (uint32_t)((i % 3) * STF) * 4u);
        }
    }

    // ---- epilogues
    if (EPI == 2) {
        float* gD = (float*)gDv;
#pragma unroll
        for (int nt = 0; nt < 4; nt++) {
            const int col = n0 + wn * 32 + nt * 8 + gc * 2;
            const float b0 = bias[col], b1 = bias[col + 1];
#pragma unroll
            for (int mt = 0; mt < 4; mt++) {
                acc[mt][nt][0] += b0; acc[mt][nt][1] += b1;
                acc[mt][nt][2] += b0; acc[mt][nt][3] += b1;
            }
        }
        if (tid < 64) redbuf[tid] = 0.f;
        __syncthreads();
#pragma unroll
        for (int mt = 0; mt < 4; mt++) {
            float p0 = 0.f, p1 = 0.f;
#pragma unroll
            for (int nt = 0; nt < 4; nt++) {
                p0 = fmaf(acc[mt][nt][0], acc[mt][nt][0], p0);
                p0 = fmaf(acc[mt][nt][1], acc[mt][nt][1], p0);
                p1 = fmaf(acc[mt][nt][2], acc[mt][nt][2], p1);
                p1 = fmaf(acc[mt][nt][3], acc[mt][nt][3], p1);
            }
            p0 += __shfl_xor_sync(0xffffffffu, p0, 1);
            p0 += __shfl_xor_sync(0xffffffffu, p0, 2);
            p1 += __shfl_xor_sync(0xffffffffu, p1, 1);
            p1 += __shfl_xor_sync(0xffffffffu, p1, 2);
            if (gc == 0) {
                atomicAdd(&redbuf[mt * 16 + gq], p0);
                atomicAdd(&redbuf[mt * 16 + gq + 8], p1);
            }
        }
        __syncthreads();
#pragma unroll
        for (int mt = 0; mt < 4; mt++) {
            const int rr = mt * 16 + gq;
            const float s0 = 1.f / (sqrtf(redbuf[rr]) + EPSF);
            const float s1 = 1.f / (sqrtf(redbuf[rr + 8]) + EPSF);
            const int r = m0 + rr;
#pragma unroll
            for (int nt = 0; nt < 4; nt++) {
                const int col = n0 + wn * 32 + nt * 8 + gc * 2;
                *(float2*)(gD + (size_t)z * sD + (size_t)r * ldd + col) =
                    make_float2(acc[mt][nt][0] * s0, acc[mt][nt][1] * s0);
                *(float2*)(gD + (size_t)z * sD + (size_t)(r + 8) * ldd + col) =
                    make_float2(acc[mt][nt][2] * s1, acc[mt][nt][3] * s1);
            }
        }
    } else {
        __half* gD = (__half*)gDv;
#pragma unroll
        for (int mt = 0; mt < 4; mt++) {
            const int r = m0 + wm * 64 + mt * 16 + gq;
            float rp0 = 0.f, rp1 = 0.f;
#pragma unroll
            for (int nt = 0; nt < 4; nt++) {
                const int col = n0 + wn * 32 + nt * 8 + gc * 2;
                float x0 = acc[mt][nt][0], x1 = acc[mt][nt][1];
                float x2 = acc[mt][nt][2], x3 = acc[mt][nt][3];
                if (EPI == 0) {
                    x0 = lrelu(x0); x1 = lrelu(x1);
                    x2 = lrelu(x2); x3 = lrelu(x3);
                    float p0 = fmaf(x0, x0, x2 * x2);
                    float p1 = fmaf(x1, x1, x3 * x3);
                    p0 += __shfl_xor_sync(0xffffffffu, p0, 4);
                    p0 += __shfl_xor_sync(0xffffffffu, p0, 8);
                    p0 += __shfl_xor_sync(0xffffffffu, p0, 16);
                    p1 += __shfl_xor_sync(0xffffffffu, p1, 4);
                    p1 += __shfl_xor_sync(0xffffffffu, p1, 8);
                    p1 += __shfl_xor_sync(0xffffffffu, p1, 16);
                    if (gq == 0) {
                        const int lc = wn * 32 + nt * 8 + gc * 2;
                        atomicAdd(&redbuf[lc], p0);
                        atomicAdd(&redbuf[lc + 1], p1);
                    }
                } else {
                    rp0 = fmaf(x0, x0, rp0); rp0 = fmaf(x1, x1, rp0);
                    rp1 = fmaf(x2, x2, rp1); rp1 = fmaf(x3, x3, rp1);
                }
                *(__half2*)(gD + (size_t)z * sD + (size_t)r * ldd + col) =
                    __floats2half2_rn(x0, x1);
                *(__half2*)(gD + (size_t)z * sD + (size_t)(r + 8) * ldd + col) =
                    __floats2half2_rn(x2, x3);
            }
            if (EPI == 1) {
                rp0 += __shfl_xor_sync(0xffffffffu, rp0, 1);
                rp0 += __shfl_xor_sync(0xffffffffu, rp0, 2);
                rp1 += __shfl_xor_sync(0xffffffffu, rp1, 1);
                rp1 += __shfl_xor_sync(0xffffffffu, rp1, 2);
                if (gc == 0) {
                    atomicAdd(&redbuf[wm * 64 + mt * 16 + gq], rp0);
                    atomicAdd(&redbuf[wm * 64 + mt * 16 + gq + 8], rp1);
                }
            }
        }
        __syncthreads();
        if (EPI == 0 && tid < TBN)
            atomicAdd(&redg[(size_t)z * LS + n0 + tid], redbuf[tid]);
        if (EPI == 1 && tid < TBM)
            atomicAdd(&redg[(size_t)z * LQ + m0 + tid], redbuf[tid]);
    }
}

// ---------------------------------------------------------------------------
// prep_all: ctx fp16 copy + transpose (tile work) + qm/W fp16 casts + zeroing,
// all packed into the (DD/32, LS/32, B_) tile grid.
// ---------------------------------------------------------------------------
__global__ __launch_bounds__(256) void prep_all_kernel(
    const float* __restrict__ ctx, const float* __restrict__ qry,
    const float* __restrict__ mat, const float* __restrict__ W)
{
    __shared__ float t[32][33];
    const int b = blockIdx.z;
    const int d0 = blockIdx.x << 5, s0 = blockIdx.y << 5;
    const int tx = threadIdx.x & 31, ty = threadIdx.x >> 5;
    const int lb = (blockIdx.z << 10) | (blockIdx.y << 5) | blockIdx.x; // 0..32767

    // --- qm stream: 128 float4 per block (threads 0..127)
    if (threadIdx.x < 128) {
        const size_t i = (size_t)lb * 128 + threadIdx.x;
        float4 a = ((const float4*)qry)[i];
        float4 m4 = ((const float4*)mat)[i];
        ((__half2*)g_qmh)[2 * i]     = __floats2half2_rn(a.x * m4.x, a.y * m4.y);
        ((__half2*)g_qmh)[2 * i + 1] = __floats2half2_rn(a.z * m4.z, a.w * m4.w);
    } else if (threadIdx.x < 130) {
        // --- W stream: 2 float4 per block
        const size_t i = (size_t)lb * 2 + (threadIdx.x - 128);
        float4 a = ((const float4*)W)[i];
        ((__half2*)g_wh)[2 * i]     = __floats2half2_rn(a.x, a.y);
        ((__half2*)g_wh)[2 * i + 1] = __floats2half2_rn(a.z, a.w);
    } else if (threadIdx.x == 130) {
        g_cn[lb] = 0.f;
    } else if (threadIdx.x == 131) {
        if (lb < B_ * LQ) g_rn[lb] = 0.f;
    }

    // --- ctx copy + transpose (all 256 threads)
    const float* src = ctx + (size_t)b * LS * DD;
    __half* dstR = g_ctxh + (size_t)b * LS * DD;
#pragma unroll
    for (int j = 0; j < 4; j++) {
        const float v = src[(size_t)(s0 + ty + j * 8) * DD + d0 + tx];
        t[ty + j * 8][tx] = v;
        dstR[(size_t)(s0 + ty + j * 8) * DD + d0 + tx] = __float2half_rn(v);
    }
    __syncthreads();
    __half* dstT = g_ctxt + (size_t)b * DD * LS;
#pragma unroll
    for (int j = 0; j < 4; j++)
        dstT[(size_t)(d0 + ty + j * 8) * LS + s0 + tx] =
            __float2half_rn(t[tx][ty + j * 8]);
}

// softmax over s per (b,q) row; smem-cached column scale; in place fp16
__global__ __launch_bounds__(256) void softmax_kernel(const int* __restrict__ smooth_ptr)
{
    __shared__ float cinv[LS];
    float sm;
    {
        int iv = *smooth_ptr;
        if (iv >= -1000000 && iv <= 1000000) sm = (float)iv;
        else                                  sm = __int_as_float(iv);
    }
    const int w = threadIdx.x >> 5, lane = threadIdx.x & 31;
    const size_t row0 = (size_t)blockIdx.x * 8;          // 8 rows, same batch
    const int b = (int)(row0 >> 9);

    {
        const float4 c = ((const float4*)(g_cn + (size_t)b * LS))[threadIdx.x];
        float4 r;
        r.x = sm / (sqrtf(c.x) + EPSF); r.y = sm / (sqrtf(c.y) + EPSF);
        r.z = sm / (sqrtf(c.z) + EPSF); r.w = sm / (sqrtf(c.w) + EPSF);
        ((float4*)cinv)[threadIdx.x] = r;
    }
    __syncthreads();

    __half2* p2 = (__half2*)(g_attn + (row0 + w) * LS);

    float v[32];
    float mx = -3.4e38f;
#pragma unroll
    for (int i = 0; i < 16; i++) {
        const int idx = i * 32 + lane;
        float2 h = __half22float2(p2[idx]);
        const float v0 = h.x * cinv[2 * idx];
        const float v1 = h.y * cinv[2 * idx + 1];
        v[2 * i] = v0; v[2 * i + 1] = v1;
        mx = fmaxf(mx, fmaxf(v0, v1));
    }
#pragma unroll
    for (int o = 16; o > 0; o >>= 1)
        mx = fmaxf(mx, __shfl_xor_sync(0xffffffffu, mx, o));
    float s = 0.f;
#pragma unroll
    for (int i = 0; i < 32; i++) {
        v[i] = __expf(v[i] - mx);
        s += v[i];
    }
#pragma unroll
    for (int o = 16; o > 0; o >>= 1)
        s += __shfl_xor_sync(0xffffffffu, s, o);
    const float inv = 1.f / s;
#pragma unroll
    for (int i = 0; i < 16; i++)
        p2[i * 32 + lane] = __floats2half2_rn(v[2 * i] * inv, v[2 * i + 1] * inv);
}

// ---------------------------------------------------------------------------
extern "C" void kernel_launch(void* const* d_in, const int* in_sizes, int n_in,
                              void* d_out, int out_size)
{
    const float* qry  = (const float*)d_in[0];
    const float* ctx  = (const float*)d_in[1];
    const float* mat  = (const float*)d_in[2];
    const float* W    = (const float*)d_in[3];
    const float* bias = (const float*)d_in[4];
    const int*   smp  = (const int*)d_in[5];
    float* outp = (float*)d_out;

    __half *pqm, *pctxh, *pctxt, *pattn, *pwch, *pwh;
    float *pcn, *prn;
    cudaGetSymbolAddress((void**)&pqm,   g_qmh);
    cudaGetSymbolAddress((void**)&pctxh, g_ctxh);
    cudaGetSymbolAddress((void**)&pctxt, g_ctxt);
    cudaGetSymbolAddress((void**)&pattn, g_attn);
    cudaGetSymbolAddress((void**)&pwch,  g_wch);
    cudaGetSymbolAddress((void**)&pwh,   g_wh);
    cudaGetSymbolAddress((void**)&pcn,   g_cn);
    cudaGetSymbolAddress((void**)&prn,   g_rn);

    constexpr int SM01 = 3 * (128 * LDB32 + 128 * LDB32) * 4 + 512;   // 111104
    constexpr int SM2  = 2 * (64 * LDB32 + 256 * LDB32) * 4 + 256;    // 92416
    cudaFuncSetAttribute(hgemm<0>, cudaFuncAttributeMaxDynamicSharedMemorySize, SM01);
    cudaFuncSetAttribute(hgemm<1>, cudaFuncAttributeMaxDynamicSharedMemorySize, SM01);
    cudaFuncSetAttribute(hgemm<2>, cudaFuncAttributeMaxDynamicSharedMemorySize, SM2);

    // 1: all prep in one launch (fp16 casts, ctx transpose, zero buffers)
    prep_all_kernel<<<dim3(DD / 32, LS / 32, B_), 256>>>(ctx, qry, mat, W);

    // 2: attn = lrelu(qm . ctx^T), fused column sumsq
    hgemm<0><<<dim3(LS / 128, LQ / 128, B_), 256, SM01>>>(
        pqm, pctxh, pattn, nullptr, pcn, nullptr, nullptr,
        DD, DD, LS, (size_t)LQ * DD, (size_t)LS * DD, (size_t)LQ * LS);

    // 3: softmax over s (smem-cached column scale)
    softmax_kernel<<<B_ * LQ / 8, 256>>>(smp);

    // 4: wc = attn . ctxT (NT), fused row sumsq  [profiled slot]
    hgemm<1><<<dim3(DD / 128, LQ / 128, B_), 256, SM01>>>(
        pattn, pctxt, pwch, nullptr, prn, nullptr, nullptr,
        LS, LS, DD, (size_t)LQ * LS, (size_t)DD * LS, (size_t)LQ * DD);

    // 5: out = diff2(wc,qry) . W^T + b, fused diff^2 A-loader + l2norm over S
    hgemm<2><<<dim3(SS / 256, LQ / 64, B_), 256, SM2>>>(
        pwch, pwh, outp, bias, nullptr, qry, prn,
        DD, DD, SS, (size_t)LQ * DD, 0, (size_t)LQ * SS);
}

// round 14
// speedup vs baseline: 1.0252x; 1.0252x over previous
#include <cuda_runtime.h>
#include <cuda_fp16.h>
#include <cstdint>
#include <math.h>

#define B_  32
#define LQ  512
#define LS  1024
#define DD  1024
#define SS  256
#define EPSF 1e-8f

// Scratch (allocation forbidden): device globals.
__device__ __half g_qmh [B_ * LQ * DD];   // fp16(query*matrix)   32MB
__device__ __half g_ctxh[B_ * LS * DD];   // fp16(ctx)            64MB
__device__ __half g_ctxt[B_ * DD * LS];   // fp16(ctx^T)          64MB
__device__ __half g_attn[B_ * LQ * LS];   // attn (b,q,s) fp16    32MB
__device__ __half g_wch [B_ * LQ * DD];   // wcontext fp16        32MB
__device__ __half g_wh  [SS * DD];        // fp16(W)              0.5MB
__device__ float  g_cn  [B_ * LS];        // column sumsq (attn)  128KB
__device__ float  g_rn  [B_ * LQ];        // row sumsq (wc)        64KB

// ---------------------------------------------------------------------------
__device__ __forceinline__ uint32_t smem_u32(const void* p) {
    uint32_t a;
    asm("{ .reg .u64 t; cvta.to.shared.u64 t, %1; cvt.u32.u64 %0, t; }"
        : "=r"(a) : "l"(p));
    return a;
}
__device__ __forceinline__ float lrelu(float x) { return x > 0.f ? x : 0.1f * x; }

__device__ __forceinline__ void cp16(uint32_t s, const void* g) {
    asm volatile("cp.async.cg.shared.global [%0], [%1], 16;" :: "r"(s), "l"(g));
}
__device__ __forceinline__ void cp_commit() {
    asm volatile("cp.async.commit_group;" ::: "memory");
}
template <int N> __device__ __forceinline__ void cp_wait() {
    asm volatile("cp.async.wait_group %0;" :: "n"(N) : "memory");
}

__device__ __forceinline__ void mma16(float* c, const uint32_t* a, const uint32_t* b) {
    asm volatile(
        "mma.sync.aligned.m16n8k16.row.col.f32.f16.f16.f32 "
        "{%0,%1,%2,%3}, {%4,%5,%6,%7}, {%8,%9}, {%0,%1,%2,%3};"
        : "+f"(c[0]), "+f"(c[1]), "+f"(c[2]), "+f"(c[3])
        : "r"(a[0]), "r"(a[1]), "r"(a[2]), "r"(a[3]), "r"(b[0]), "r"(b[1]));
}
__device__ __forceinline__ void ldsm4(uint32_t* r, uint32_t addr) {
    asm volatile("ldmatrix.sync.aligned.m8n8.x4.shared.b16 {%0,%1,%2,%3}, [%4];"
        : "=r"(r[0]), "=r"(r[1]), "=r"(r[2]), "=r"(r[3]) : "r"(addr));
}

// ---------------------------------------------------------------------------
// fp16 warp-MMA GEMM: D[m,n] = sum_k A[m,k]*B[n,k]  (K=1024, both K-major)
//   EPI 0: CTA 128x128 occ2, 3-stage cp.async. leaky_relu, fp16 store,
//          fused column-sumsq.
//   EPI 1: CTA 128x128 occ2, 3-stage cp.async. fp16 store, fused row-sumsq.
//   EPI 2: CTA 64x256 occ2, 2-stage. A = diff^2 fused loader (wc,qry,rn).
//          +bias, fused l2norm over N=256, fp32 store.
// ---------------------------------------------------------------------------
#define KTOT 1024
#define BKC  64
#define NIT  (KTOT / BKC)       // 16
#define LDB32 36                // row pitch, b32 units
#define ROWB  (LDB32 * 4)       // 144 B

template <int EPI>
__global__ __launch_bounds__(256, 2) void hgemm(
    const __half* __restrict__ gA, const __half* __restrict__ gB,
    void* __restrict__ gDv, const float* __restrict__ bias,
    float* __restrict__ redg,
    const float* __restrict__ qy, const float* __restrict__ rn,
    int lda, int ldb, int ldd, size_t sA, size_t sB, size_t sD)
{
    constexpr int TBM = (EPI == 2) ? 64 : 128;
    constexpr int TBN = (EPI == 2) ? 256 : 128;
    constexpr int TWM = (EPI == 2) ? 1 : 2;
    constexpr int NST = (EPI == 2) ? 2 : 3;
    constexpr int AF  = TBM * LDB32;
    constexpr int BF  = TBN * LDB32;
    constexpr int STF = AF + BF;

    extern __shared__ uint32_t smu[];
    float* redbuf = (float*)(smu + NST * STF);

    const int tid  = threadIdx.x;
    const int wid  = tid >> 5, lane = tid & 31;
    const int m0   = blockIdx.y * TBM, n0 = blockIdx.x * TBN, z = blockIdx.z;
    const int wm   = wid % TWM;
    const int wn   = wid / TWM;
    const int gq   = lane >> 2;
    const int gc   = lane & 3;

    const __half* A  = gA + (size_t)z * sA + (size_t)m0 * lda;
    const __half* Bp = gB + (size_t)z * sB + (size_t)n0 * ldb;
    const uint32_t sbase = smem_u32(smu);

    const int lr = lane & 7;
    const uint32_t aoff = (uint32_t)(wm * 64 + lr + ((lane >> 3) & 1) * 8) * ROWB
                        + (uint32_t)(lane >> 4) * 16;
    const uint32_t boff = (uint32_t)(wn * 32 + lr + (lane >> 4) * 8) * ROWB
                        + (uint32_t)((lane >> 3) & 1) * 16 + (uint32_t)AF * 4u;

    if (EPI == 0 && tid < TBN) redbuf[tid] = 0.f;
    if (EPI == 1 && tid < TBM) redbuf[tid] = 0.f;

    // EPI2 fused-A state: thread owns row am, 16 halfs at [aseg*8, aseg*8+16)
    const int am   = tid >> 2;
    const int aseg = (tid & 3) * 2;
    float ainv = 0.f;
    const __half* wcrow = nullptr;
    const float*  qrow  = nullptr;
    if (EPI == 2) {
        ainv  = 1.f / (sqrtf(rn[(size_t)z * LQ + m0 + am]) + EPSF);
        wcrow = gA + (size_t)z * sA + (size_t)(m0 + am) * lda;
        qrow  = qy + (size_t)z * sA + (size_t)(m0 + am) * lda;
    }

    float acc[4][4][4];
#pragma unroll
    for (int i = 0; i < 4; i++)
#pragma unroll
        for (int j = 0; j < 4; j++)
#pragma unroll
            for (int k = 0; k < 4; k++) acc[i][j][k] = 0.f;

    auto load_stage = [&](int stage, int k0) {
        const uint32_t ab = sbase + (uint32_t)(stage * STF) * 4u;
        const uint32_t bb = ab + (uint32_t)AF * 4u;
        if (EPI == 2) {
            // A: diff^2 computed on the fly (sync loads; occ 2 hides latency)
            const __half2* wh = (const __half2*)(wcrow + k0 + aseg * 8);
            const float4 q0 = *(const float4*)(qrow + k0 + aseg * 8);
            const float4 q1 = *(const float4*)(qrow + k0 + aseg * 8 + 4);
            const float4 q2 = *(const float4*)(qrow + k0 + aseg * 8 + 8);
            const float4 q3 = *(const float4*)(qrow + k0 + aseg * 8 + 12);
            const float qq[16] = {q0.x,q0.y,q0.z,q0.w, q1.x,q1.y,q1.z,q1.w,
                                  q2.x,q2.y,q2.z,q2.w, q3.x,q3.y,q3.z,q3.w};
            uint32_t out[8];
#pragma unroll
            for (int j = 0; j < 8; j++) {
                const float2 wf = __half22float2(wh[j]);
                const float d0 = qq[2 * j]     - wf.x * ainv;
                const float d1 = qq[2 * j + 1] - wf.y * ainv;
                const __half2 r = __floats2half2_rn(d0 * d0, d1 * d1);
                out[j] = *(const uint32_t*)&r;
            }
            char* sm8 = (char*)smu + (size_t)stage * STF * 4 + am * ROWB + aseg * 16;
            *(uint4*)sm8        = *(const uint4*)&out[0];
            *(uint4*)(sm8 + 16) = *(const uint4*)&out[4];
        } else {
#pragma unroll
            for (int r = 0; r < TBM * 8 / 256; r++) {
                int u = tid + r * 256;
                int m = u >> 3, seg = u & 7;
                cp16(ab + (uint32_t)(m * ROWB + seg * 16),
                     A + (size_t)m * lda + k0 + seg * 8);
            }
        }
#pragma unroll
        for (int r = 0; r < TBN * 8 / 256; r++) {
            int u = tid + r * 256;
            int n = u >> 3, seg = u & 7;
            cp16(bb + (uint32_t)(n * ROWB + seg * 16),
                 Bp + (size_t)n * ldb + k0 + seg * 8);
        }
        cp_commit();
    };

    auto compute = [&](uint32_t stA) {
#pragma unroll
        for (int ks = 0; ks < 4; ks++) {
            uint32_t af[4][4], bf[4][2];
#pragma unroll
            for (int mt = 0; mt < 4; mt++)
                ldsm4(af[mt], stA + ks * 32 + aoff + (uint32_t)(mt * 16 * ROWB));
#pragma unroll
            for (int np = 0; np < 2; np++) {
                uint32_t t[4];
                ldsm4(t, stA + ks * 32 + boff + (uint32_t)(np * 16 * ROWB));
                bf[np * 2][0] = t[0]; bf[np * 2][1] = t[1];
                bf[np * 2 + 1][0] = t[2]; bf[np * 2 + 1][1] = t[3];
            }
#pragma unroll
            for (int mt = 0; mt < 4; mt++)
#pragma unroll
                for (int nt = 0; nt < 4; nt++)
                    mma16(acc[mt][nt], af[mt], bf[nt]);
        }
    };

    if (EPI == 2) {
        load_stage(0, 0);
        for (int i = 0; i < NIT; i++) {
            cp_wait<0>();
            __syncthreads();
            if (i + 1 < NIT) load_stage((i + 1) & 1, (i + 1) * BKC);
            compute(sbase + (uint32_t)((i & 1) * STF) * 4u);
        }
    } else {
        load_stage(0, 0);
        load_stage(1, BKC);
        for (int i = 0; i < NIT; i++) {
            if (i < NIT - 1) cp_wait<1>(); else cp_wait<0>();
            __syncthreads();
            if (i + 2 < NIT) load_stage((i + 2) % 3, (i + 2) * BKC);
            compute(sbase + (uint32_t)((i % 3) * STF) * 4u);
        }
    }

    // ---- epilogues
    if (EPI == 2) {
        float* gD = (float*)gDv;
#pragma unroll
        for (int nt = 0; nt < 4; nt++) {
            const int col = n0 + wn * 32 + nt * 8 + gc * 2;
            const float b0 = bias[col], b1 = bias[col + 1];
#pragma unroll
            for (int mt = 0; mt < 4; mt++) {
                acc[mt][nt][0] += b0; acc[mt][nt][1] += b1;
                acc[mt][nt][2] += b0; acc[mt][nt][3] += b1;
            }
        }
        if (tid < 64) redbuf[tid] = 0.f;
        __syncthreads();
#pragma unroll
        for (int mt = 0; mt < 4; mt++) {
            float p0 = 0.f, p1 = 0.f;
#pragma unroll
            for (int nt = 0; nt < 4; nt++) {
                p0 = fmaf(acc[mt][nt][0], acc[mt][nt][0], p0);
                p0 = fmaf(acc[mt][nt][1], acc[mt][nt][1], p0);
                p1 = fmaf(acc[mt][nt][2], acc[mt][nt][2], p1);
                p1 = fmaf(acc[mt][nt][3], acc[mt][nt][3], p1);
            }
            p0 += __shfl_xor_sync(0xffffffffu, p0, 1);
            p0 += __shfl_xor_sync(0xffffffffu, p0, 2);
            p1 += __shfl_xor_sync(0xffffffffu, p1, 1);
            p1 += __shfl_xor_sync(0xffffffffu, p1, 2);
            if (gc == 0) {
                atomicAdd(&redbuf[mt * 16 + gq], p0);
                atomicAdd(&redbuf[mt * 16 + gq + 8], p1);
            }
        }
        __syncthreads();
#pragma unroll
        for (int mt = 0; mt < 4; mt++) {
            const int rr = mt * 16 + gq;
            const float s0 = 1.f / (sqrtf(redbuf[rr]) + EPSF);
            const float s1 = 1.f / (sqrtf(redbuf[rr + 8]) + EPSF);
            const int r = m0 + rr;
#pragma unroll
            for (int nt = 0; nt < 4; nt++) {
                const int col = n0 + wn * 32 + nt * 8 + gc * 2;
                *(float2*)(gD + (size_t)z * sD + (size_t)r * ldd + col) =
                    make_float2(acc[mt][nt][0] * s0, acc[mt][nt][1] * s0);
                *(float2*)(gD + (size_t)z * sD + (size_t)(r + 8) * ldd + col) =
                    make_float2(acc[mt][nt][2] * s1, acc[mt][nt][3] * s1);
            }
        }
    } else {
        __half* gD = (__half*)gDv;
#pragma unroll
        for (int mt = 0; mt < 4; mt++) {
            const int r = m0 + wm * 64 + mt * 16 + gq;
            float rp0 = 0.f, rp1 = 0.f;
#pragma unroll
            for (int nt = 0; nt < 4; nt++) {
                const int col = n0 + wn * 32 + nt * 8 + gc * 2;
                float x0 = acc[mt][nt][0], x1 = acc[mt][nt][1];
                float x2 = acc[mt][nt][2], x3 = acc[mt][nt][3];
                if (EPI == 0) {
                    x0 = lrelu(x0); x1 = lrelu(x1);
                    x2 = lrelu(x2); x3 = lrelu(x3);
                    float p0 = fmaf(x0, x0, x2 * x2);
                    float p1 = fmaf(x1, x1, x3 * x3);
                    p0 += __shfl_xor_sync(0xffffffffu, p0, 4);
                    p0 += __shfl_xor_sync(0xffffffffu, p0, 8);
                    p0 += __shfl_xor_sync(0xffffffffu, p0, 16);
                    p1 += __shfl_xor_sync(0xffffffffu, p1, 4);
                    p1 += __shfl_xor_sync(0xffffffffu, p1, 8);
                    p1 += __shfl_xor_sync(0xffffffffu, p1, 16);
                    if (gq == 0) {
                        const int lc = wn * 32 + nt * 8 + gc * 2;
                        atomicAdd(&redbuf[lc], p0);
                        atomicAdd(&redbuf[lc + 1], p1);
                    }
                } else {
                    rp0 = fmaf(x0, x0, rp0); rp0 = fmaf(x1, x1, rp0);
                    rp1 = fmaf(x2, x2, rp1); rp1 = fmaf(x3, x3, rp1);
                }
                *(__half2*)(gD + (size_t)z * sD + (size_t)r * ldd + col) =
                    __floats2half2_rn(x0, x1);
                *(__half2*)(gD + (size_t)z * sD + (size_t)(r + 8) * ldd + col) =
                    __floats2half2_rn(x2, x3);
            }
            if (EPI == 1) {
                rp0 += __shfl_xor_sync(0xffffffffu, rp0, 1);
                rp0 += __shfl_xor_sync(0xffffffffu, rp0, 2);
                rp1 += __shfl_xor_sync(0xffffffffu, rp1, 1);
                rp1 += __shfl_xor_sync(0xffffffffu, rp1, 2);
                if (gc == 0) {
                    atomicAdd(&redbuf[wm * 64 + mt * 16 + gq], rp0);
                    atomicAdd(&redbuf[wm * 64 + mt * 16 + gq + 8], rp1);
                }
            }
        }
        __syncthreads();
        if (EPI == 0 && tid < TBN)
            atomicAdd(&redg[(size_t)z * LS + n0 + tid], redbuf[tid]);
        if (EPI == 1 && tid < TBM)
            atomicAdd(&redg[(size_t)z * LQ + m0 + tid], redbuf[tid]);
    }
}

// ---------------------------------------------------------------------------
// Elementwise / prep kernels
// ---------------------------------------------------------------------------
__global__ __launch_bounds__(256) void prep_qm_kernel(
    const float* __restrict__ q, const float* __restrict__ m)
{
    size_t i = (size_t)blockIdx.x * 256 + threadIdx.x;
    float4 a = ((const float4*)q)[i];
    float4 b = ((const float4*)m)[i];
    ((__half2*)g_qmh)[2 * i]     = __floats2half2_rn(a.x * b.x, a.y * b.y);
    ((__half2*)g_qmh)[2 * i + 1] = __floats2half2_rn(a.z * b.z, a.w * b.w);
}

// ctx -> fp16 copy + fp16 transpose; 64s x 32d tiles, float2/half2 accesses
__global__ __launch_bounds__(256) void prep_ctx_kernel(const float* __restrict__ ctx)
{
    __shared__ float t[32][66];            // [d][s], pitch 66 floats
    const int b  = blockIdx.z;
    const int d0 = blockIdx.x << 5;        // 32 d per tile
    const int s0 = blockIdx.y << 6;        // 64 s per tile
    const int tx2 = threadIdx.x & 15;      // d-pair index 0..15
    const int sr  = threadIdx.x >> 4;      // 0..15
    const float* src = ctx + (size_t)b * LS * DD;
    __half2* dstR = (__half2*)(g_ctxh + (size_t)b * LS * DD);
#pragma unroll
    for (int j = 0; j < 4; j++) {
        const int s = s0 + sr + j * 16;
        const float2 v = *(const float2*)(src + (size_t)s * DD + d0 + tx2 * 2);
        dstR[((size_t)s * DD + d0 + tx2 * 2) >> 1] = __floats2half2_rn(v.x, v.y);
        t[tx2 * 2][sr + j * 16]     = v.x;
        t[tx2 * 2 + 1][sr + j * 16] = v.y;
    }
    __syncthreads();
    __half2* dstT = (__half2*)(g_ctxt + (size_t)b * DD * LS);
    const int dd = threadIdx.x >> 5;       // 0..7
    const int sp = threadIdx.x & 31;       // s-pair 0..31
#pragma unroll
    for (int j = 0; j < 4; j++) {
        const int d = dd + j * 8;
        const float2 v = *(const float2*)&t[d][sp * 2];
        dstT[((size_t)(d0 + d) * LS + s0 + sp * 2) >> 1] =
            __floats2half2_rn(v.x, v.y);
    }
}

// fp16(W), also zeros the reduction buffers
__global__ __launch_bounds__(256) void prep_w_kernel(const float* __restrict__ W)
{
    size_t i = (size_t)blockIdx.x * 256 + threadIdx.x;
    float4 a = ((const float4*)W)[i];
    ((__half2*)g_wh)[2 * i]     = __floats2half2_rn(a.x, a.y);
    ((__half2*)g_wh)[2 * i + 1] = __floats2half2_rn(a.z, a.w);
    if (i < B_ * LS) g_cn[i] = 0.f;
    if (i < B_ * LQ) g_rn[i] = 0.f;
}

// softmax over s per (b,q) row; smem-cached column scale; in place fp16
__global__ __launch_bounds__(256) void softmax_kernel(const int* __restrict__ smooth_ptr)
{
    __shared__ float cinv[LS];
    float sm;
    {
        int iv = *smooth_ptr;
        if (iv >= -1000000 && iv <= 1000000) sm = (float)iv;
        else                                  sm = __int_as_float(iv);
    }
    const int w = threadIdx.x >> 5, lane = threadIdx.x & 31;
    const size_t row0 = (size_t)blockIdx.x * 8;          // 8 rows, same batch
    const int b = (int)(row0 >> 9);

    {
        const float4 c = ((const float4*)(g_cn + (size_t)b * LS))[threadIdx.x];
        float4 r;
        r.x = sm / (sqrtf(c.x) + EPSF); r.y = sm / (sqrtf(c.y) + EPSF);
        r.z = sm / (sqrtf(c.z) + EPSF); r.w = sm / (sqrtf(c.w) + EPSF);
        ((float4*)cinv)[threadIdx.x] = r;
    }
    __syncthreads();

    __half2* p2 = (__half2*)(g_attn + (row0 + w) * LS);

    float v[32];
    float mx = -3.4e38f;
#pragma unroll
    for (int i = 0; i < 16; i++) {
        const int idx = i * 32 + lane;
        float2 h = __half22float2(p2[idx]);
        const float v0 = h.x * cinv[2 * idx];
        const float v1 = h.y * cinv[2 * idx + 1];
        v[2 * i] = v0; v[2 * i + 1] = v1;
        mx = fmaxf(mx, fmaxf(v0, v1));
    }
#pragma unroll
    for (int o = 16; o > 0; o >>= 1)
        mx = fmaxf(mx, __shfl_xor_sync(0xffffffffu, mx, o));
    float s = 0.f;
#pragma unroll
    for (int i = 0; i < 32; i++) {
        v[i] = __expf(v[i] - mx);
        s += v[i];
    }
#pragma unroll
    for (int o = 16; o > 0; o >>= 1)
        s += __shfl_xor_sync(0xffffffffu, s, o);
    const float inv = 1.f / s;
#pragma unroll
    for (int i = 0; i < 16; i++)
        p2[i * 32 + lane] = __floats2half2_rn(v[2 * i] * inv, v[2 * i + 1] * inv);
}

// ---------------------------------------------------------------------------
extern "C" void kernel_launch(void* const* d_in, const int* in_sizes, int n_in,
                              void* d_out, int out_size)
{
    const float* qry  = (const float*)d_in[0];
    const float* ctx  = (const float*)d_in[1];
    const float* mat  = (const float*)d_in[2];
    const float* W    = (const float*)d_in[3];
    const float* bias = (const float*)d_in[4];
    const int*   smp  = (const int*)d_in[5];
    float* outp = (float*)d_out;

    __half *pqm, *pctxh, *pctxt, *pattn, *pwch, *pwh;
    float *pcn, *prn;
    cudaGetSymbolAddress((void**)&pqm,   g_qmh);
    cudaGetSymbolAddress((void**)&pctxh, g_ctxh);
    cudaGetSymbolAddress((void**)&pctxt, g_ctxt);
    cudaGetSymbolAddress((void**)&pattn, g_attn);
    cudaGetSymbolAddress((void**)&pwch,  g_wch);
    cudaGetSymbolAddress((void**)&pwh,   g_wh);
    cudaGetSymbolAddress((void**)&pcn,   g_cn);
    cudaGetSymbolAddress((void**)&prn,   g_rn);

    constexpr int SM01 = 3 * (128 * LDB32 + 128 * LDB32) * 4 + 512;   // 111104
    constexpr int SM2  = 2 * (64 * LDB32 + 256 * LDB32) * 4 + 256;    // 92416
    cudaFuncSetAttribute(hgemm<0>, cudaFuncAttributeMaxDynamicSharedMemorySize, SM01);
    cudaFuncSetAttribute(hgemm<1>, cudaFuncAttributeMaxDynamicSharedMemorySize, SM01);
    cudaFuncSetAttribute(hgemm<2>, cudaFuncAttributeMaxDynamicSharedMemorySize, SM2);

    // 1-3: prep (fp16 casts + vectorized ctx transpose, zero reduction buffers)
    prep_qm_kernel<<<(B_ * LQ * DD) / 4 / 256, 256>>>(qry, mat);
    prep_ctx_kernel<<<dim3(DD / 32, LS / 64, B_), 256>>>(ctx);
    prep_w_kernel<<<(SS * DD) / 4 / 256, 256>>>(W);

    // 4: attn = lrelu(qm . ctx^T), fused column sumsq  [profiled slot]
    hgemm<0><<<dim3(LS / 128, LQ / 128, B_), 256, SM01>>>(
        pqm, pctxh, pattn, nullptr, pcn, nullptr, nullptr,
        DD, DD, LS, (size_t)LQ * DD, (size_t)LS * DD, (size_t)LQ * LS);

    // 5: softmax over s (smem-cached column scale)
    softmax_kernel<<<B_ * LQ / 8, 256>>>(smp);

    // 6: wc = attn . ctxT (NT), fused row sumsq
    hgemm<1><<<dim3(DD / 128, LQ / 128, B_), 256, SM01>>>(
        pattn, pctxt, pwch, nullptr, prn, nullptr, nullptr,
        LS, LS, DD, (size_t)LQ * LS, (size_t)DD * LS, (size_t)LQ * DD);

    // 7: out = diff2(wc,qry) . W^T + b, fused diff^2 A-loader + l2norm over S
    hgemm<2><<<dim3(SS / 256, LQ / 64, B_), 256, SM2>>>(
        pwch, pwh, outp, bias, nullptr, qry, prn,
        DD, DD, SS, (size_t)LQ * DD, 0, (size_t)LQ * SS);
}

// round 16
// speedup vs baseline: 1.0293x; 1.0041x over previous
#include <cuda_runtime.h>
#include <cuda_fp16.h>
#include <cstdint>
#include <math.h>

#define B_  32
#define LQ  512
#define LS  1024
#define DD  1024
#define SS  256
#define EPSF 1e-8f

// Scratch (allocation forbidden): device globals.
__device__ __half g_qmh [B_ * LQ * DD];   // fp16(query*matrix)   32MB
__device__ __half g_ctxh[B_ * LS * DD];   // fp16(ctx)            64MB
__device__ __half g_ctxt[B_ * DD * LS];   // fp16(ctx^T)          64MB
__device__ __half g_attn[B_ * LQ * LS];   // attn (b,q,s) fp16    32MB
__device__ __half g_wch [B_ * LQ * DD];   // wcontext fp16        32MB
__device__ __half g_wh  [SS * DD];        // fp16(W)              0.5MB
__device__ float  g_cn  [B_ * LS];        // column sumsq (attn)  128KB
__device__ float  g_rn  [B_ * LQ];        // row sumsq (wc)        64KB

// ---------------------------------------------------------------------------
__device__ __forceinline__ uint32_t smem_u32(const void* p) {
    uint32_t a;
    asm("{ .reg .u64 t; cvta.to.shared.u64 t, %1; cvt.u32.u64 %0, t; }"
        : "=r"(a) : "l"(p));
    return a;
}
__device__ __forceinline__ float lrelu(float x) { return x > 0.f ? x : 0.1f * x; }

__device__ __forceinline__ void cp16(uint32_t s, const void* g) {
    asm volatile("cp.async.cg.shared.global [%0], [%1], 16;" :: "r"(s), "l"(g));
}
__device__ __forceinline__ void cp_commit() {
    asm volatile("cp.async.commit_group;" ::: "memory");
}
template <int N> __device__ __forceinline__ void cp_wait() {
    asm volatile("cp.async.wait_group %0;" :: "n"(N) : "memory");
}

__device__ __forceinline__ void mma16(float* c, const uint32_t* a, const uint32_t* b) {
    asm volatile(
        "mma.sync.aligned.m16n8k16.row.col.f32.f16.f16.f32 "
        "{%0,%1,%2,%3}, {%4,%5,%6,%7}, {%8,%9}, {%0,%1,%2,%3};"
        : "+f"(c[0]), "+f"(c[1]), "+f"(c[2]), "+f"(c[3])
        : "r"(a[0]), "r"(a[1]), "r"(a[2]), "r"(a[3]), "r"(b[0]), "r"(b[1]));
}
__device__ __forceinline__ void ldsm4(uint32_t* r, uint32_t addr) {
    asm volatile("ldmatrix.sync.aligned.m8n8.x4.shared.b16 {%0,%1,%2,%3}, [%4];"
        : "=r"(r[0]), "=r"(r[1]), "=r"(r[2]), "=r"(r[3]) : "r"(addr));
}

// ---------------------------------------------------------------------------
// fp16 warp-MMA GEMM: D[m,n] = sum_k A[m,k]*B[n,k]  (K=1024, both K-major)
//   EPI 0: CTA 128x128 occ2, 3-stage cp.async. leaky_relu, fp16 store,
//          fused column-sumsq.
//   EPI 1: CTA 128x128 occ2, 3-stage cp.async. fp16 store, fused row-sumsq.
//   EPI 2: CTA 64x256 occ2, 2-stage. A = diff^2 fused loader (wc,qry,rn).
//          +bias, fused l2norm over N=256, fp32 store.
// ---------------------------------------------------------------------------
#define KTOT 1024
#define BKC  64
#define NIT  (KTOT / BKC)       // 16
#define LDB32 36                // row pitch, b32 units
#define ROWB  (LDB32 * 4)       // 144 B

template <int EPI>
__global__ __launch_bounds__(256, 2) void hgemm(
    const __half* __restrict__ gA, const __half* __restrict__ gB,
    void* __restrict__ gDv, const float* __restrict__ bias,
    float* __restrict__ redg,
    const float* __restrict__ qy, const float* __restrict__ rn,
    int lda, int ldb, int ldd, size_t sA, size_t sB, size_t sD)
{
    constexpr int TBM = (EPI == 2) ? 64 : 128;
    constexpr int TBN = (EPI == 2) ? 256 : 128;
    constexpr int TWM = (EPI == 2) ? 1 : 2;
    constexpr int NST = (EPI == 2) ? 2 : 3;
    constexpr int AF  = TBM * LDB32;
    constexpr int BF  = TBN * LDB32;
    constexpr int STF = AF + BF;

    extern __shared__ uint32_t smu[];
    float* redbuf = (float*)(smu + NST * STF);

    const int tid  = threadIdx.x;
    const int wid  = tid >> 5, lane = tid & 31;
    const int m0   = blockIdx.y * TBM, n0 = blockIdx.x * TBN, z = blockIdx.z;
    const int wm   = wid % TWM;
    const int wn   = wid / TWM;
    const int gq   = lane >> 2;
    const int gc   = lane & 3;

    const __half* A  = gA + (size_t)z * sA + (size_t)m0 * lda;
    const __half* Bp = gB + (size_t)z * sB + (size_t)n0 * ldb;
    const uint32_t sbase = smem_u32(smu);

    const int lr = lane & 7;
    const uint32_t aoff = (uint32_t)(wm * 64 + lr + ((lane >> 3) & 1) * 8) * ROWB
                        + (uint32_t)(lane >> 4) * 16;
    const uint32_t boff = (uint32_t)(wn * 32 + lr + (lane >> 4) * 8) * ROWB
                        + (uint32_t)((lane >> 3) & 1) * 16 + (uint32_t)AF * 4u;

    if (EPI == 0 && tid < TBN) redbuf[tid] = 0.f;
    if (EPI == 1 && tid < TBM) redbuf[tid] = 0.f;

    // EPI2 fused-A state: thread owns row am, 16 halfs at [aseg*8, aseg*8+16)
    const int am   = tid >> 2;
    const int aseg = (tid & 3) * 2;
    float ainv = 0.f;
    const __half* wcrow = nullptr;
    const float*  qrow  = nullptr;
    if (EPI == 2) {
        ainv  = 1.f / (sqrtf(rn[(size_t)z * LQ + m0 + am]) + EPSF);
        wcrow = gA + (size_t)z * sA + (size_t)(m0 + am) * lda;
        qrow  = qy + (size_t)z * sA + (size_t)(m0 + am) * lda;
    }

    float acc[4][4][4];
#pragma unroll
    for (int i = 0; i < 4; i++)
#pragma unroll
        for (int j = 0; j < 4; j++)
#pragma unroll
            for (int k = 0; k < 4; k++) acc[i][j][k] = 0.f;

    auto load_stage = [&](int stage, int k0) {
        const uint32_t ab = sbase + (uint32_t)(stage * STF) * 4u;
        const uint32_t bb = ab + (uint32_t)AF * 4u;
        if (EPI == 2) {
            // A: diff^2 computed on the fly (sync loads; occ 2 hides latency)
            const __half2* wh = (const __half2*)(wcrow + k0 + aseg * 8);
            const float4 q0 = *(const float4*)(qrow + k0 + aseg * 8);
            const float4 q1 = *(const float4*)(qrow + k0 + aseg * 8 + 4);
            const float4 q2 = *(const float4*)(qrow + k0 + aseg * 8 + 8);
            const float4 q3 = *(const float4*)(qrow + k0 + aseg * 8 + 12);
            const float qq[16] = {q0.x,q0.y,q0.z,q0.w, q1.x,q1.y,q1.z,q1.w,
                                  q2.x,q2.y,q2.z,q2.w, q3.x,q3.y,q3.z,q3.w};
            uint32_t out[8];
#pragma unroll
            for (int j = 0; j < 8; j++) {
                const float2 wf = __half22float2(wh[j]);
                const float d0 = qq[2 * j]     - wf.x * ainv;
                const float d1 = qq[2 * j + 1] - wf.y * ainv;
                const __half2 r = __floats2half2_rn(d0 * d0, d1 * d1);
                out[j] = *(const uint32_t*)&r;
            }
            char* sm8 = (char*)smu + (size_t)stage * STF * 4 + am * ROWB + aseg * 16;
            *(uint4*)sm8        = *(const uint4*)&out[0];
            *(uint4*)(sm8 + 16) = *(const uint4*)&out[4];
        } else {
#pragma unroll
            for (int r = 0; r < TBM * 8 / 256; r++) {
                int u = tid + r * 256;
                int m = u >> 3, seg = u & 7;
                cp16(ab + (uint32_t)(m * ROWB + seg * 16),
                     A + (size_t)m * lda + k0 + seg * 8);
            }
        }
#pragma unroll
        for (int r = 0; r < TBN * 8 / 256; r++) {
            int u = tid + r * 256;
            int n = u >> 3, seg = u & 7;
            cp16(bb + (uint32_t)(n * ROWB + seg * 16),
                 Bp + (size_t)n * ldb + k0 + seg * 8);
        }
        cp_commit();
    };

    auto compute = [&](uint32_t stA) {
#pragma unroll
        for (int ks = 0; ks < 4; ks++) {
            uint32_t af[4][4], bf[4][2];
#pragma unroll
            for (int mt = 0; mt < 4; mt++)
                ldsm4(af[mt], stA + ks * 32 + aoff + (uint32_t)(mt * 16 * ROWB));
#pragma unroll
            for (int np = 0; np < 2; np++) {
                uint32_t t[4];
                ldsm4(t, stA + ks * 32 + boff + (uint32_t)(np * 16 * ROWB));
                bf[np * 2][0] = t[0]; bf[np * 2][1] = t[1];
                bf[np * 2 + 1][0] = t[2]; bf[np * 2 + 1][1] = t[3];
            }
#pragma unroll
            for (int mt = 0; mt < 4; mt++)
#pragma unroll
                for (int nt = 0; nt < 4; nt++)
                    mma16(acc[mt][nt], af[mt], bf[nt]);
        }
    };

    if (EPI == 2) {
        load_stage(0, 0);
        for (int i = 0; i < NIT; i++) {
            cp_wait<0>();
            __syncthreads();
            if (i + 1 < NIT) load_stage((i + 1) & 1, (i + 1) * BKC);
            compute(sbase + (uint32_t)((i & 1) * STF) * 4u);
        }
    } else {
        load_stage(0, 0);
        load_stage(1, BKC);
        for (int i = 0; i < NIT; i++) {
            if (i < NIT - 1) cp_wait<1>(); else cp_wait<0>();
            __syncthreads();
            if (i + 2 < NIT) load_stage((i + 2) % 3, (i + 2) * BKC);
            compute(sbase + (uint32_t)((i % 3) * STF) * 4u);
        }
    }

    // ---- epilogues
    if (EPI == 2) {
        float* gD = (float*)gDv;
#pragma unroll
        for (int nt = 0; nt < 4; nt++) {
            const int col = n0 + wn * 32 + nt * 8 + gc * 2;
            const float b0 = bias[col], b1 = bias[col + 1];
#pragma unroll
            for (int mt = 0; mt < 4; mt++) {
                acc[mt][nt][0] += b0; acc[mt][nt][1] += b1;
                acc[mt][nt][2] += b0; acc[mt][nt][3] += b1;
            }
        }
        if (tid < 64) redbuf[tid] = 0.f;
        __syncthreads();
#pragma unroll
        for (int mt = 0; mt < 4; mt++) {
            float p0 = 0.f, p1 = 0.f;
#pragma unroll
            for (int nt = 0; nt < 4; nt++) {
                p0 = fmaf(acc[mt][nt][0], acc[mt][nt][0], p0);
                p0 = fmaf(acc[mt][nt][1], acc[mt][nt][1], p0);
                p1 = fmaf(acc[mt][nt][2], acc[mt][nt][2], p1);
                p1 = fmaf(acc[mt][nt][3], acc[mt][nt][3], p1);
            }
            p0 += __shfl_xor_sync(0xffffffffu, p0, 1);
            p0 += __shfl_xor_sync(0xffffffffu, p0, 2);
            p1 += __shfl_xor_sync(0xffffffffu, p1, 1);
            p1 += __shfl_xor_sync(0xffffffffu, p1, 2);
            if (gc == 0) {
                atomicAdd(&redbuf[mt * 16 + gq], p0);
                atomicAdd(&redbuf[mt * 16 + gq + 8], p1);
            }
        }
        __syncthreads();
#pragma unroll
        for (int mt = 0; mt < 4; mt++) {
            const int rr = mt * 16 + gq;
            const float s0 = 1.f / (sqrtf(redbuf[rr]) + EPSF);
            const float s1 = 1.f / (sqrtf(redbuf[rr + 8]) + EPSF);
            const int r = m0 + rr;
#pragma unroll
            for (int nt = 0; nt < 4; nt++) {
                const int col = n0 + wn * 32 + nt * 8 + gc * 2;
                *(float2*)(gD + (size_t)z * sD + (size_t)r * ldd + col) =
                    make_float2(acc[mt][nt][0] * s0, acc[mt][nt][1] * s0);
                *(float2*)(gD + (size_t)z * sD + (size_t)(r + 8) * ldd + col) =
                    make_float2(acc[mt][nt][2] * s1, acc[mt][nt][3] * s1);
            }
        }
    } else {
        __half* gD = (__half*)gDv;
#pragma unroll
        for (int mt = 0; mt < 4; mt++) {
            const int r = m0 + wm * 64 + mt * 16 + gq;
            float rp0 = 0.f, rp1 = 0.f;
#pragma unroll
            for (int nt = 0; nt < 4; nt++) {
                const int col = n0 + wn * 32 + nt * 8 + gc * 2;
                float x0 = acc[mt][nt][0], x1 = acc[mt][nt][1];
                float x2 = acc[mt][nt][2], x3 = acc[mt][nt][3];
                if (EPI == 0) {
                    x0 = lrelu(x0); x1 = lrelu(x1);
                    x2 = lrelu(x2); x3 = lrelu(x3);
                    float p0 = fmaf(x0, x0, x2 * x2);
                    float p1 = fmaf(x1, x1, x3 * x3);
                    p0 += __shfl_xor_sync(0xffffffffu, p0, 4);
                    p0 += __shfl_xor_sync(0xffffffffu, p0, 8);
                    p0 += __shfl_xor_sync(0xffffffffu, p0, 16);
                    p1 += __shfl_xor_sync(0xffffffffu, p1, 4);
                    p1 += __shfl_xor_sync(0xffffffffu, p1, 8);
                    p1 += __shfl_xor_sync(0xffffffffu, p1, 16);
                    if (gq == 0) {
                        const int lc = wn * 32 + nt * 8 + gc * 2;
                        atomicAdd(&redbuf[lc], p0);
                        atomicAdd(&redbuf[lc + 1], p1);
                    }
                } else {
                    rp0 = fmaf(x0, x0, rp0); rp0 = fmaf(x1, x1, rp0);
                    rp1 = fmaf(x2, x2, rp1); rp1 = fmaf(x3, x3, rp1);
                }
                *(__half2*)(gD + (size_t)z * sD + (size_t)r * ldd + col) =
                    __floats2half2_rn(x0, x1);
                *(__half2*)(gD + (size_t)z * sD + (size_t)(r + 8) * ldd + col) =
                    __floats2half2_rn(x2, x3);
            }
            if (EPI == 1) {
                rp0 += __shfl_xor_sync(0xffffffffu, rp0, 1);
                rp0 += __shfl_xor_sync(0xffffffffu, rp0, 2);
                rp1 += __shfl_xor_sync(0xffffffffu, rp1, 1);
                rp1 += __shfl_xor_sync(0xffffffffu, rp1, 2);
                if (gc == 0) {
                    atomicAdd(&redbuf[wm * 64 + mt * 16 + gq], rp0);
                    atomicAdd(&redbuf[wm * 64 + mt * 16 + gq + 8], rp1);
                }
            }
        }
        __syncthreads();
        if (EPI == 0 && tid < TBN)
            atomicAdd(&redg[(size_t)z * LS + n0 + tid], redbuf[tid]);
        if (EPI == 1 && tid < TBM)
            atomicAdd(&redg[(size_t)z * LQ + m0 + tid], redbuf[tid]);
    }
}

// ---------------------------------------------------------------------------
// Elementwise / prep kernels
// ---------------------------------------------------------------------------
// qm = fp16(query*matrix); side streams: fp16(W) + zero cn/rn (block-indexed)
__global__ __launch_bounds__(256) void prep_qm_kernel(
    const float* __restrict__ q, const float* __restrict__ m,
    const float* __restrict__ W)
{
    size_t i = (size_t)blockIdx.x * 256 + threadIdx.x;
    float4 a = ((const float4*)q)[i];
    float4 b = ((const float4*)m)[i];
    ((__half2*)g_qmh)[2 * i]     = __floats2half2_rn(a.x * b.x, a.y * b.y);
    ((__half2*)g_qmh)[2 * i + 1] = __floats2half2_rn(a.z * b.z, a.w * b.w);

    if (blockIdx.x < 256) {                      // W: 65536 float4 over 256 blocks
        const size_t j = (size_t)blockIdx.x * 256 + threadIdx.x;
        float4 w4 = ((const float4*)W)[j];
        ((__half2*)g_wh)[2 * j]     = __floats2half2_rn(w4.x, w4.y);
        ((__half2*)g_wh)[2 * j + 1] = __floats2half2_rn(w4.z, w4.w);
    } else if (blockIdx.x < 384) {               // cn: 32768 floats over 128 blocks
        g_cn[(blockIdx.x - 256) * 256 + threadIdx.x] = 0.f;
    } else if (blockIdx.x < 448) {               // rn: 16384 floats over 64 blocks
        g_rn[(blockIdx.x - 384) * 256 + threadIdx.x] = 0.f;
    }
}

// ctx -> fp16 copy + fp16 transpose; 64s x 32d tiles, float2/half2 accesses
// (R14-proven version: scalar smem staging, no alignment hazards)
__global__ __launch_bounds__(256) void prep_ctx_kernel(const float* __restrict__ ctx)
{
    __shared__ float t[32][66];            // [d][s], pitch 66 floats
    const int b  = blockIdx.z;
    const int d0 = blockIdx.x << 5;        // 32 d per tile
    const int s0 = blockIdx.y << 6;        // 64 s per tile
    const int tx2 = threadIdx.x & 15;      // d-pair index 0..15
    const int sr  = threadIdx.x >> 4;      // 0..15
    const float* src = ctx + (size_t)b * LS * DD;
    __half2* dstR = (__half2*)(g_ctxh + (size_t)b * LS * DD);
#pragma unroll
    for (int j = 0; j < 4; j++) {
        const int s = s0 + sr + j * 16;
        const float2 v = *(const float2*)(src + (size_t)s * DD + d0 + tx2 * 2);
        dstR[((size_t)s * DD + d0 + tx2 * 2) >> 1] = __floats2half2_rn(v.x, v.y);
        t[tx2 * 2][sr + j * 16]     = v.x;
        t[tx2 * 2 + 1][sr + j * 16] = v.y;
    }
    __syncthreads();
    __half2* dstT = (__half2*)(g_ctxt + (size_t)b * DD * LS);
    const int dd = threadIdx.x >> 5;       // 0..7
    const int sp = threadIdx.x & 31;       // s-pair 0..31
#pragma unroll
    for (int j = 0; j < 4; j++) {
        const int d = dd + j * 8;
        const float2 v = *(const float2*)&t[d][sp * 2];
        dstT[((size_t)(d0 + d) * LS + s0 + sp * 2) >> 1] =
            __floats2half2_rn(v.x, v.y);
    }
}

// softmax over s; 512 threads = 16 rows/block sharing the cinv table
__global__ __launch_bounds__(512) void softmax_kernel(const int* __restrict__ smooth_ptr)
{
    __shared__ float cinv[LS];
    float sm;
    {
        int iv = *smooth_ptr;
        if (iv >= -1000000 && iv <= 1000000) sm = (float)iv;
        else                                  sm = __int_as_float(iv);
    }
    const int w = threadIdx.x >> 5, lane = threadIdx.x & 31;
    const size_t row0 = (size_t)blockIdx.x * 16;         // 16 rows, same batch
    const int b = (int)(row0 >> 9);

    // precompute sm / (sqrt(cn) + eps) once per block (512 thr x 2 floats)
    {
        const float2 c = ((const float2*)(g_cn + (size_t)b * LS))[threadIdx.x];
        float2 r;
        r.x = sm / (sqrtf(c.x) + EPSF); r.y = sm / (sqrtf(c.y) + EPSF);
        ((float2*)cinv)[threadIdx.x] = r;
    }
    __syncthreads();

    __half2* p2 = (__half2*)(g_attn + (row0 + w) * LS);

    float v[32];
    float mx = -3.4e38f;
#pragma unroll
    for (int i = 0; i < 16; i++) {
        const int idx = i * 32 + lane;
        float2 h = __half22float2(p2[idx]);
        const float v0 = h.x * cinv[2 * idx];
        const float v1 = h.y * cinv[2 * idx + 1];
        v[2 * i] = v0; v[2 * i + 1] = v1;
        mx = fmaxf(mx, fmaxf(v0, v1));
    }
#pragma unroll
    for (int o = 16; o > 0; o >>= 1)
        mx = fmaxf(mx, __shfl_xor_sync(0xffffffffu, mx, o));
    float s = 0.f;
#pragma unroll
    for (int i = 0; i < 32; i++) {
        v[i] = __expf(v[i] - mx);
        s += v[i];
    }
#pragma unroll
    for (int o = 16; o > 0; o >>= 1)
        s += __shfl_xor_sync(0xffffffffu, s, o);
    const float inv = 1.f / s;
#pragma unroll
    for (int i = 0; i < 16; i++)
        p2[i * 32 + lane] = __floats2half2_rn(v[2 * i] * inv, v[2 * i + 1] * inv);
}

// ---------------------------------------------------------------------------
extern "C" void kernel_launch(void* const* d_in, const int* in_sizes, int n_in,
                              void* d_out, int out_size)
{
    const float* qry  = (const float*)d_in[0];
    const float* ctx  = (const float*)d_in[1];
    const float* mat  = (const float*)d_in[2];
    const float* W    = (const float*)d_in[3];
    const float* bias = (const float*)d_in[4];
    const int*   smp  = (const int*)d_in[5];
    float* outp = (float*)d_out;

    __half *pqm, *pctxh, *pctxt, *pattn, *pwch, *pwh;
    float *pcn, *prn;
    cudaGetSymbolAddress((void**)&pqm,   g_qmh);
    cudaGetSymbolAddress((void**)&pctxh, g_ctxh);
    cudaGetSymbolAddress((void**)&pctxt, g_ctxt);
    cudaGetSymbolAddress((void**)&pattn, g_attn);
    cudaGetSymbolAddress((void**)&pwch,  g_wch);
    cudaGetSymbolAddress((void**)&pwh,   g_wh);
    cudaGetSymbolAddress((void**)&pcn,   g_cn);
    cudaGetSymbolAddress((void**)&prn,   g_rn);

    constexpr int SM01 = 3 * (128 * LDB32 + 128 * LDB32) * 4 + 512;   // 111104
    constexpr int SM2  = 2 * (64 * LDB32 + 256 * LDB32) * 4 + 256;    // 92416
    cudaFuncSetAttribute(hgemm<0>, cudaFuncAttributeMaxDynamicSharedMemorySize, SM01);
    cudaFuncSetAttribute(hgemm<1>, cudaFuncAttributeMaxDynamicSharedMemorySize, SM01);
    cudaFuncSetAttribute(hgemm<2>, cudaFuncAttributeMaxDynamicSharedMemorySize, SM2);

    // 1-2: prep (qm fp16 + W fp16 + zero buffers; ctx fp16 copy + transpose)
    prep_qm_kernel<<<(B_ * LQ * DD) / 4 / 256, 256>>>(qry, mat, W);
    prep_ctx_kernel<<<dim3(DD / 32, LS / 64, B_), 256>>>(ctx);

    // 3: attn = lrelu(qm . ctx^T), fused column sumsq  [profiled slot]
    hgemm<0><<<dim3(LS / 128, LQ / 128, B_), 256, SM01>>>(
        pqm, pctxh, pattn, nullptr, pcn, nullptr, nullptr,
        DD, DD, LS, (size_t)LQ * DD, (size_t)LS * DD, (size_t)LQ * LS);

    // 4: softmax over s (16 rows/block, shared cinv)
    softmax_kernel<<<B_ * LQ / 16, 512>>>(smp);

    // 5: wc = attn . ctxT (NT), fused row sumsq
    hgemm<1><<<dim3(DD / 128, LQ / 128, B_), 256, SM01>>>(
        pattn, pctxt, pwch, nullptr, prn, nullptr, nullptr,
        LS, LS, DD, (size_t)LQ * LS, (size_t)DD * LS, (size_t)LQ * DD);

    // 6: out = diff2(wc,qry) . W^T + b, fused diff^2 A-loader + l2norm over S
    hgemm<2><<<dim3(SS / 256, LQ / 64, B_), 256, SM2>>>(
        pwch, pwh, outp, bias, nullptr, qry, prn,
        DD, DD, SS, (size_t)LQ * DD, 0, (size_t)LQ * SS);
}